// round 7
// baseline (speedup 1.0000x reference)
#include <cuda_runtime.h>
#include <mma.h>
#include <cstdint>

using namespace nvcuda;

// ---------------- problem constants ----------------
#define B_SZ  64
#define L_SZ  512
#define IN_SZ 512
#define MEM   1024

// ---------------- device scratch ----------------
__device__ float g_emb[(size_t)L_SZ * B_SZ * 3 * MEM];  // [t][b][3*MEM], fp32
__device__ float g_h[2][B_SZ * MEM];                    // double-buffered exact fp32 h
__device__ unsigned g_bar;

// ---------------- helpers ----------------
__device__ __forceinline__ float f2tf32f(float f) {
    unsigned u;
    asm("cvt.rna.tf32.f32 %0, %1;" : "=r"(u) : "f"(f));
    return __uint_as_float(u);
}
__device__ __forceinline__ void split_tf32(float x, float& hi, float& lo) {
    hi = f2tf32f(x);
    lo = f2tf32f(x - hi);
}
__device__ __forceinline__ void split4(float4 v, float4& h, float4& l) {
    split_tf32(v.x, h.x, l.x); split_tf32(v.y, h.y, l.y);
    split_tf32(v.z, h.z, l.z); split_tf32(v.w, h.w, l.w);
}
__device__ __forceinline__ float4 ldcg_f4(const float* p) {
    float4 v;
    asm volatile("ld.global.cg.v4.f32 {%0,%1,%2,%3}, [%4];"
                 : "=f"(v.x), "=f"(v.y), "=f"(v.z), "=f"(v.w) : "l"(p));
    return v;
}
__device__ __forceinline__ void stcg_f2(float* p, float a, float b) {
    asm volatile("st.global.cg.v2.f32 [%0], {%1,%2};" :: "l"(p), "f"(a), "f"(b) : "memory");
}

// ---------------- init ----------------
__global__ void init_kernel() {
    int i = blockIdx.x * blockDim.x + threadIdx.x;
    if (i == 0) g_bar = 0u;
    for (int k = i; k < B_SZ * MEM; k += gridDim.x * blockDim.x) {
        g_h[0][k] = 0.0f;
        g_h[1][k] = 0.0f;
    }
}

// ---------------- input projection GEMM (wmma 3xTF32) ----------------
// C[r][j] = sum_k u[r][k] * W_im[j][k], r = b*L + l; stored g_emb[(l*64+b)*3072 + j]
#define GAS 40
#define GSMEM ((128 * GAS * 2 + 64 * GAS * 2) * 4)   // 61440 B

__global__ __launch_bounds__(256) void gemm_in(const float* __restrict__ u,
                                               const float* __restrict__ Wim) {
    extern __shared__ float sm[];
    float* Ah = sm;                   // [128][40]
    float* Al = Ah + 128 * GAS;
    float* Bh = Al + 128 * GAS;       // [64][40]
    float* Bl = Bh + 64 * GAS;

    const int m0 = blockIdx.y * 128;
    const int n0 = blockIdx.x * 64;
    const int t = threadIdx.x;
    const int w = t >> 5;
    const int lane = t & 31;
    const int wm = w >> 1, wn = w & 1;     // 4 x 2 warp grid, warp tile 32x32

    wmma::fragment<wmma::accumulator, 16, 16, 8, float> c[2][2];
#pragma unroll
    for (int mi = 0; mi < 2; mi++)
#pragma unroll
        for (int ni = 0; ni < 2; ni++) wmma::fill_fragment(c[mi][ni], 0.0f);

    for (int k0 = 0; k0 < IN_SZ; k0 += 32) {
#pragma unroll
        for (int p = 0; p < 4; p++) {       // A: 128x32 = 1024 float4
            int f4 = t + p * 256;
            int row = f4 >> 3, c4 = (f4 & 7) * 4;
            float4 v = *(const float4*)(u + (size_t)(m0 + row) * IN_SZ + k0 + c4);
            float4 h, l; split4(v, h, l);
            *(float4*)(Ah + row * GAS + c4) = h;
            *(float4*)(Al + row * GAS + c4) = l;
        }
#pragma unroll
        for (int p = 0; p < 2; p++) {       // B: 64x32 = 512 float4
            int f4 = t + p * 256;
            int row = f4 >> 3, c4 = (f4 & 7) * 4;
            float4 v = *(const float4*)(Wim + (size_t)(n0 + row) * IN_SZ + k0 + c4);
            float4 h, l; split4(v, h, l);
            *(float4*)(Bh + row * GAS + c4) = h;
            *(float4*)(Bl + row * GAS + c4) = l;
        }
        __syncthreads();

#pragma unroll
        for (int kk = 0; kk < 32; kk += 8) {
            wmma::fragment<wmma::matrix_a, 16, 16, 8, wmma::precision::tf32, wmma::row_major> ah[2], al[2];
            wmma::fragment<wmma::matrix_b, 16, 16, 8, wmma::precision::tf32, wmma::col_major> bh[2], bl[2];
#pragma unroll
            for (int mi = 0; mi < 2; mi++) {
                wmma::load_matrix_sync(ah[mi], Ah + (wm * 32 + mi * 16) * GAS + kk, GAS);
                wmma::load_matrix_sync(al[mi], Al + (wm * 32 + mi * 16) * GAS + kk, GAS);
            }
#pragma unroll
            for (int ni = 0; ni < 2; ni++) {
                wmma::load_matrix_sync(bh[ni], Bh + (wn * 32 + ni * 16) * GAS + kk, GAS);
                wmma::load_matrix_sync(bl[ni], Bl + (wn * 32 + ni * 16) * GAS + kk, GAS);
            }
#pragma unroll
            for (int mi = 0; mi < 2; mi++)
#pragma unroll
                for (int ni = 0; ni < 2; ni++) {
                    wmma::mma_sync(c[mi][ni], ah[mi], bh[ni], c[mi][ni]);
                    wmma::mma_sync(c[mi][ni], ah[mi], bl[ni], c[mi][ni]);
                    wmma::mma_sync(c[mi][ni], al[mi], bh[ni], c[mi][ni]);
                }
        }
        __syncthreads();
    }

    // epilogue: C -> smem (per-warp region) -> scalar writes to g_emb
    float* Cs = sm + w * (32 * 36);          // [32][36] per warp
#pragma unroll
    for (int mi = 0; mi < 2; mi++)
#pragma unroll
        for (int ni = 0; ni < 2; ni++)
            wmma::store_matrix_sync(Cs + (mi * 16) * 36 + ni * 16, c[mi][ni], 36,
                                    wmma::mem_row_major);
    __syncwarp();

    int gr = m0 + wm * 32 + lane;            // global row = b*L + l
    int b = gr >> 9, l = gr & 511;
    float* dst = g_emb + ((size_t)((l << 6) + b)) * (3 * MEM) + n0 + wn * 32;
#pragma unroll
    for (int cc = 0; cc < 32; cc += 4)
        *(float4*)(dst + cc) = *(const float4*)(Cs + lane * 36 + cc);
}

// ---------------- persistent recurrence (wmma 3xTF32) ----------------
// 128 CTAs; CTA g owns mem cols [g*8, g*8+8). B = [8 Wa rows ; 8 Wc rows] (16 wide).
// Per step: C(64x16) = h(64x1024) @ B^T, then gated update.
#define JT 8
#define NCTA 128
#define RTHREADS 256
#define WLD 1032
#define ALD 136
#define CLD 24
#define WS_HI 0
#define WS_LO 16512
#define AS_HI 33024
#define AS_LO 41728
#define CS_OF 50432
#define RSMEM (51968 * 4)   // 207,872 B

__global__ __launch_bounds__(RTHREADS, 1) void recur(const float* __restrict__ Wmm,
                                                     float* __restrict__ out_seq,
                                                     float* __restrict__ out_last) {
    extern __shared__ float sm[];
    float* Wh_s = sm + WS_HI;   // [16][1032]
    float* Wl_s = sm + WS_LO;
    float* Ah_s = sm + AS_HI;   // [64][136]
    float* Al_s = sm + AS_LO;
    float* Cs_s = sm + CS_OF;   // [64][24]

    const int t = threadIdx.x;
    const int w = t >> 5;
    const int g = blockIdx.x;
    const int j0 = g * JT;

    // prologue: stage W slice (rows 0..7 = Wa[j0..], rows 8..15 = Wc[MEM+j0..]), split hi/lo
    for (int i = t; i < 16 * 256; i += RTHREADS) {
        int row = i >> 8;
        int c4 = (i & 255) * 4;
        int wrow = (row < 8) ? (j0 + row) : (MEM + j0 + (row - 8));
        float4 v = *(const float4*)(Wmm + (size_t)wrow * MEM + c4);
        float4 h, l; split4(v, h, l);
        *(float4*)(Wh_s + row * WLD + c4) = h;
        *(float4*)(Wl_s + row * WLD + c4) = l;
    }

    // elementwise cell ownership: cells = t*2, t*2+1 -> b = t>>2, j = (t*2)&7 (even)
    const int eb = t >> 2;
    const int ej = (t * 2) & 7;
    float h0 = 0.0f, h1 = 0.0f;

    __syncthreads();

    unsigned bar_target = 0;

    for (int step = 0; step < L_SZ; step++) {
        const float* h_rd = g_h[step & 1];
        float*       h_wr = g_h[(step & 1) ^ 1];

        wmma::fragment<wmma::accumulator, 16, 16, 8, float> fc;
        wmma::fill_fragment(fc, 0.0f);

        for (int kc = 0; kc < 8; kc++) {
            // stage h chunk [64][128] via L2 (cg), split hi/lo
            for (int i = t; i < 2048; i += RTHREADS) {
                int b = i >> 5, c4 = (i & 31) * 4;
                float4 v = ldcg_f4(h_rd + (size_t)b * MEM + kc * 128 + c4);
                float4 h, l; split4(v, h, l);
                *(float4*)(Ah_s + b * ALD + c4) = h;
                *(float4*)(Al_s + b * ALD + c4) = l;
            }
            __syncthreads();

            if (w < 4) {   // warp w: batch rows w*16 .. w*16+15
#pragma unroll
                for (int kk = 0; kk < 16; kk++) {
                    int k8 = kk * 8;
                    wmma::fragment<wmma::matrix_a, 16, 16, 8, wmma::precision::tf32, wmma::row_major> fa_h, fa_l;
                    wmma::fragment<wmma::matrix_b, 16, 16, 8, wmma::precision::tf32, wmma::col_major> fb_h, fb_l;
                    wmma::load_matrix_sync(fa_h, Ah_s + (w * 16) * ALD + k8, ALD);
                    wmma::load_matrix_sync(fa_l, Al_s + (w * 16) * ALD + k8, ALD);
                    wmma::load_matrix_sync(fb_h, Wh_s + kc * 128 + k8, WLD);
                    wmma::load_matrix_sync(fb_l, Wl_s + kc * 128 + k8, WLD);
                    wmma::mma_sync(fc, fa_h, fb_h, fc);
                    wmma::mma_sync(fc, fa_h, fb_l, fc);
                    wmma::mma_sync(fc, fa_l, fb_h, fc);
                }
            }
            __syncthreads();
        }

        if (w < 4)
            wmma::store_matrix_sync(Cs_s + (w * 16) * CLD, fc, CLD, wmma::mem_row_major);
        __syncthreads();

        // ---- elementwise gated update (2 adjacent cells per thread) ----
        {
            float m_a0 = Cs_s[eb * CLD + ej];
            float m_a1 = Cs_s[eb * CLD + ej + 1];
            float m_c0 = Cs_s[eb * CLD + 8 + ej];
            float m_c1 = Cs_s[eb * CLD + 8 + ej + 1];
            const float* e = g_emb + ((size_t)step * B_SZ + eb) * (3 * MEM) + j0 + ej;
            float2 iA = __ldg((const float2*)e);
            float2 iC = __ldg((const float2*)(e + MEM));
            float2 iO = __ldg((const float2*)(e + 2 * MEM));

            float aa0 = 1.0f + tanhf(iA.x + m_a0);
            float cc0 = 1.0f / (1.0f + expf(-(iC.x + m_c0)));
            float hn0 = cc0 * h0 + (1.0f - cc0) * tanhf(iO.x + aa0 * h0);
            float aa1 = 1.0f + tanhf(iA.y + m_a1);
            float cc1 = 1.0f / (1.0f + expf(-(iC.y + m_c1)));
            float hn1 = cc1 * h1 + (1.0f - cc1) * tanhf(iO.y + aa1 * h1);
            h0 = hn0; h1 = hn1;

            float* os = out_seq + ((size_t)eb * L_SZ + step) * MEM + j0 + ej;
            *(float2*)os = make_float2(hn0, hn1);
            if (step == L_SZ - 1)
                *(float2*)(out_last + (size_t)eb * MEM + j0 + ej) = make_float2(hn0, hn1);
            stcg_f2(h_wr + (size_t)eb * MEM + j0 + ej, hn0, hn1);
        }

        // ---- grid barrier: release -> count -> acquire spin ----
        __threadfence();
        __syncthreads();
        bar_target += NCTA;
        if (t == 0) {
            asm volatile("red.release.gpu.global.add.u32 [%0], %1;"
                         :: "l"(&g_bar), "r"(1u) : "memory");
            unsigned v;
            do {
                asm volatile("ld.acquire.gpu.global.u32 %0, [%1];"
                             : "=r"(v) : "l"(&g_bar) : "memory");
            } while (v < bar_target);
        }
        __syncthreads();
        __threadfence();
    }
}

// ---------------- launch ----------------
extern "C" void kernel_launch(void* const* d_in, const int* in_sizes, int n_in,
                              void* d_out, int out_size) {
    const float* u   = (const float*)d_in[0];
    const float* Wim = (const float*)d_in[1];
    const float* Wmm = (const float*)d_in[2];
    float* out = (float*)d_out;
    float* out_seq  = out;
    float* out_last = out + (size_t)B_SZ * L_SZ * MEM;

    init_kernel<<<64, 256>>>();

    cudaFuncSetAttribute(gemm_in, cudaFuncAttributeMaxDynamicSharedMemorySize, GSMEM);
    dim3 ggrid((3 * MEM) / 64, (B_SZ * L_SZ) / 128);   // 48 x 256
    gemm_in<<<ggrid, 256, GSMEM>>>(u, Wim);

    cudaFuncSetAttribute(recur, cudaFuncAttributeMaxDynamicSharedMemorySize, RSMEM);
    recur<<<NCTA, RTHREADS, RSMEM>>>(Wmm, out_seq, out_last);
}

// round 12
// speedup vs baseline: 1.6264x; 1.6264x over previous
#include <cuda_runtime.h>
#include <mma.h>
#include <cstdint>

using namespace nvcuda;

// ---------------- problem constants ----------------
#define B_SZ  64
#define L_SZ  512
#define IN_SZ 512
#define MEM   1024

// ---------------- device scratch ----------------
__device__ float g_emb[(size_t)L_SZ * B_SZ * 3 * MEM];  // [t][b][3*MEM], fp32
__device__ float g_h[2][B_SZ * MEM];                    // double-buffered exact fp32 h
__device__ unsigned g_bar;

// ---------------- helpers ----------------
__device__ __forceinline__ float f2tf32f(float f) {
    unsigned u;
    asm("cvt.rna.tf32.f32 %0, %1;" : "=r"(u) : "f"(f));
    return __uint_as_float(u);
}
__device__ __forceinline__ void split_tf32(float x, float& hi, float& lo) {
    hi = f2tf32f(x);
    lo = f2tf32f(x - hi);
}
__device__ __forceinline__ void split4(float4 v, float4& h, float4& l) {
    split_tf32(v.x, h.x, l.x); split_tf32(v.y, h.y, l.y);
    split_tf32(v.z, h.z, l.z); split_tf32(v.w, h.w, l.w);
}
__device__ __forceinline__ void stcg_f2(float* p, float a, float b) {
    asm volatile("st.global.cg.v2.f32 [%0], {%1,%2};" :: "l"(p), "f"(a), "f"(b) : "memory");
}
__device__ __forceinline__ void cp_async16(void* smem_dst, const void* gsrc) {
    unsigned s = (unsigned)__cvta_generic_to_shared(smem_dst);
    asm volatile("cp.async.cg.shared.global [%0], [%1], 16;\n" :: "r"(s), "l"(gsrc));
}
__device__ __forceinline__ void cp_commit() { asm volatile("cp.async.commit_group;\n"); }
template <int N>
__device__ __forceinline__ void cp_wait() { asm volatile("cp.async.wait_group %0;\n" :: "n"(N)); }

// split a tf32 fragment elementwise (raw fp32 bits in) -> hi/lo tf32 fragments
template <typename FragT>
__device__ __forceinline__ void split_frag(const FragT& raw, FragT& hi, FragT& lo) {
#pragma unroll
    for (int e = 0; e < raw.num_elements; e++) {
        float h, l;
        split_tf32(raw.x[e], h, l);
        hi.x[e] = h;
        lo.x[e] = l;
    }
}

// ---------------- init ----------------
__global__ void init_kernel() {
    int i = blockIdx.x * blockDim.x + threadIdx.x;
    if (i == 0) g_bar = 0u;
    for (int k = i; k < B_SZ * MEM; k += gridDim.x * blockDim.x) {
        g_h[0][k] = 0.0f;
        g_h[1][k] = 0.0f;
    }
}

// ---------------- input projection GEMM (wmma 3xTF32, cp.async pipelined) ----------------
// C[r][j] = sum_k u[r][k] * W_im[j][k], r = b*L + l; stored g_emb[(l*64+b)*3072 + j]
#define GLD 36
#define GA_OF 0
#define GB_OF (2 * 128 * GLD)
#define GSMEM ((2 * 128 * GLD + 2 * 64 * GLD) * 4)   // 55,296 B

__global__ __launch_bounds__(256) void gemm_in(const float* __restrict__ u,
                                               const float* __restrict__ Wim) {
    extern __shared__ float sm[];
    float* As = sm + GA_OF;     // [2][128][GLD] raw fp32
    float* Bs = sm + GB_OF;     // [2][64][GLD]  raw fp32

    const int m0 = blockIdx.y * 128;
    const int n0 = blockIdx.x * 64;
    const int t = threadIdx.x;
    const int w = t >> 5;
    const int lane = t & 31;
    const int wm = w >> 1, wn = w & 1;   // 4x2 warp grid, warp tile 32x32

    wmma::fragment<wmma::accumulator, 16, 16, 8, float> c[2][2];
#pragma unroll
    for (int mi = 0; mi < 2; mi++)
#pragma unroll
        for (int ni = 0; ni < 2; ni++) wmma::fill_fragment(c[mi][ni], 0.0f);

    auto issue_chunk = [&](int ck) {
        int buf = ck & 1;
        int k0 = ck * 32;
#pragma unroll
        for (int p = 0; p < 4; p++) {     // A: 128x32 = 1024 f4
            int i = t + p * 256;
            int row = i >> 3, c4 = (i & 7) * 4;
            cp_async16(As + buf * 128 * GLD + row * GLD + c4,
                       u + (size_t)(m0 + row) * IN_SZ + k0 + c4);
        }
#pragma unroll
        for (int p = 0; p < 2; p++) {     // B: 64x32 = 512 f4
            int i = t + p * 256;
            int row = i >> 3, c4 = (i & 7) * 4;
            cp_async16(Bs + buf * 64 * GLD + row * GLD + c4,
                       Wim + (size_t)(n0 + row) * IN_SZ + k0 + c4);
        }
        cp_commit();
    };

    issue_chunk(0);

    for (int ck = 0; ck < 16; ck++) {
        if (ck < 15) issue_chunk(ck + 1);
        if (ck < 15) cp_wait<1>(); else cp_wait<0>();
        __syncthreads();

        const float* Ab = As + (ck & 1) * 128 * GLD;
        const float* Bb = Bs + (ck & 1) * 64 * GLD;
#pragma unroll
        for (int kk = 0; kk < 32; kk += 8) {
            wmma::fragment<wmma::matrix_a, 16, 16, 8, wmma::precision::tf32, wmma::row_major> ar, ah[2], al[2];
            wmma::fragment<wmma::matrix_b, 16, 16, 8, wmma::precision::tf32, wmma::col_major> br, bh[2], bl[2];
#pragma unroll
            for (int mi = 0; mi < 2; mi++) {
                wmma::load_matrix_sync(ar, Ab + (wm * 32 + mi * 16) * GLD + kk, GLD);
                split_frag(ar, ah[mi], al[mi]);
            }
#pragma unroll
            for (int ni = 0; ni < 2; ni++) {
                wmma::load_matrix_sync(br, Bb + (wn * 32 + ni * 16) * GLD + kk, GLD);
                split_frag(br, bh[ni], bl[ni]);
            }
#pragma unroll
            for (int mi = 0; mi < 2; mi++)
#pragma unroll
                for (int ni = 0; ni < 2; ni++) {
                    wmma::mma_sync(c[mi][ni], ah[mi], bh[ni], c[mi][ni]);
                    wmma::mma_sync(c[mi][ni], ah[mi], bl[ni], c[mi][ni]);
                    wmma::mma_sync(c[mi][ni], al[mi], bh[ni], c[mi][ni]);
                }
        }
        __syncthreads();
    }

    // epilogue: C -> smem (per-warp region) -> coalesced writes to g_emb
    float* Cs = sm + w * (32 * 36);      // [32][36] per warp
#pragma unroll
    for (int mi = 0; mi < 2; mi++)
#pragma unroll
        for (int ni = 0; ni < 2; ni++)
            wmma::store_matrix_sync(Cs + (mi * 16) * 36 + ni * 16, c[mi][ni], 36,
                                    wmma::mem_row_major);
    __syncwarp();

    int gr = m0 + wm * 32 + lane;        // global row = b*L + l
    int b = gr >> 9, l = gr & 511;
    float* dst = g_emb + ((size_t)((l << 6) + b)) * (3 * MEM) + n0 + wn * 32;
#pragma unroll
    for (int cc = 0; cc < 32; cc += 4)
        *(float4*)(dst + cc) = *(const float4*)(Cs + lane * 36 + cc);
}

// ---------------- persistent recurrence (128 CTAs, 8-warp split-K, cp.async) ----------------
// CTA g owns cols [g*8, g*8+8). B tile (N=16): rows 0-7 = Wa[j0..], 8-15 = Wc[MEM+j0..].
// Warp (bw = w&1, ks = w>>1): bw picks batch rows [bw*32, bw*32+32),
// ks picks k-quarter [ks*32, ks*32+32) within each 128-k chunk.
// Partials Cp[4][64][16] summed in elementwise phase.
#define JT 8
#define NCTA 128
#define RTHREADS 256
#define WLD 1032
#define ALD 132
#define CPLD 20
#define WH_OF 0
#define WL_OF (16 * WLD)                        // 16512
#define AH_OF (2 * 16 * WLD)                    // 33024, [2][64][ALD]
#define ABUF  (B_SZ * ALD)                      // 8448 floats per buffer
#define CP_OF (AH_OF + 2 * ABUF)                // 49920, [4][64][CPLD]
#define RSMEM ((CP_OF + 4 * B_SZ * CPLD) * 4)   // 220,160 B

__global__ __launch_bounds__(RTHREADS, 1) void recur(const float* __restrict__ Wmm,
                                                     float* __restrict__ out_seq,
                                                     float* __restrict__ out_last) {
    extern __shared__ float sm[];
    float* Wh_s = sm + WH_OF;   // [16][WLD] hi
    float* Wl_s = sm + WL_OF;   // [16][WLD] lo
    float* Ah_s = sm + AH_OF;   // [2][64][ALD] raw fp32 h chunk
    float* Cp_s = sm + CP_OF;   // [4][64][CPLD] split-K partials

    const int t = threadIdx.x;
    const int w = t >> 5;
    const int bw = w & 1;       // batch group: rows [bw*32, bw*32+32)
    const int ks = w >> 1;      // k quarter within chunk
    const int g = blockIdx.x;
    const int j0 = g * JT;

    // prologue: stage W slice pre-split (rows 0..7 = Wa, 8..15 = Wc)
    for (int i = t; i < 16 * 256; i += RTHREADS) {
        int row = i >> 8;
        int c4 = (i & 255) * 4;
        int wrow = (row < 8) ? (j0 + row) : (MEM + j0 + (row - 8));
        float4 v = *(const float4*)(Wmm + (size_t)wrow * MEM + c4);
        float4 h, l; split4(v, h, l);
        *(float4*)(Wh_s + row * WLD + c4) = h;
        *(float4*)(Wl_s + row * WLD + c4) = l;
    }

    // elementwise ownership: b = t>>2, j = (t&3)*2 (+0,+1): 2 cells/thread
    const int eb = t >> 2;
    const int ej = (t & 3) * 2;
    float h0 = 0.0f, h1 = 0.0f;

    __syncthreads();

    unsigned bar_target = 0;

    for (int step = 0; step < L_SZ; step++) {
        const float* h_rd = g_h[step & 1];
        float*       h_wr = g_h[(step & 1) ^ 1];

        // prefetch emb operands (independent of h) — hidden under the MMA loop
        const float* e = g_emb + ((size_t)step * B_SZ + eb) * (3 * MEM) + j0 + ej;
        float2 iA = __ldg((const float2*)e);
        float2 iC = __ldg((const float2*)(e + MEM));
        float2 iO = __ldg((const float2*)(e + 2 * MEM));

        wmma::fragment<wmma::accumulator, 16, 16, 8, float> fc[2];
        wmma::fill_fragment(fc[0], 0.0f);
        wmma::fill_fragment(fc[1], 0.0f);

        // issue h chunk 0 (cp.async.cg = L2-coherent, bypasses L1)
        {
#pragma unroll
            for (int p = 0; p < 8; p++) {
                int i = t + p * 256;
                int b = i >> 5, c4 = (i & 31) * 4;
                cp_async16(Ah_s + b * ALD + c4, h_rd + (size_t)b * MEM + c4);
            }
            cp_commit();
        }

        for (int kc = 0; kc < 8; kc++) {
            if (kc < 7) {   // prefetch next chunk into other buffer
                float* dst = Ah_s + ((kc + 1) & 1) * ABUF;
                const float* src = h_rd + (kc + 1) * 128;
#pragma unroll
                for (int p = 0; p < 8; p++) {
                    int i = t + p * 256;
                    int b = i >> 5, c4 = (i & 31) * 4;
                    cp_async16(dst + b * ALD + c4, src + (size_t)b * MEM + c4);
                }
                cp_commit();
            }
            if (kc < 7) cp_wait<1>(); else cp_wait<0>();
            __syncthreads();

            const float* Ab = Ah_s + (kc & 1) * ABUF;
            const int kbase = kc * 128 + ks * 32;
#pragma unroll
            for (int kk = 0; kk < 4; kk++) {
                const int k8 = kk * 8;
                wmma::fragment<wmma::matrix_a, 16, 16, 8, wmma::precision::tf32, wmma::row_major> ar, ah[2], al[2];
                wmma::fragment<wmma::matrix_b, 16, 16, 8, wmma::precision::tf32, wmma::col_major> fb_h, fb_l;
#pragma unroll
                for (int mi = 0; mi < 2; mi++) {
                    wmma::load_matrix_sync(ar, Ab + (bw * 32 + mi * 16) * ALD + ks * 32 + k8, ALD);
                    split_frag(ar, ah[mi], al[mi]);
                }
                wmma::load_matrix_sync(fb_h, Wh_s + kbase + k8, WLD);
                wmma::load_matrix_sync(fb_l, Wl_s + kbase + k8, WLD);
#pragma unroll
                for (int mi = 0; mi < 2; mi++) {
                    wmma::mma_sync(fc[mi], ah[mi], fb_h, fc[mi]);
                    wmma::mma_sync(fc[mi], ah[mi], fb_l, fc[mi]);
                    wmma::mma_sync(fc[mi], al[mi], fb_h, fc[mi]);
                }
            }
            __syncthreads();   // compute done before next chunk overwrites buffer
        }

        // store split-K partials
#pragma unroll
        for (int mi = 0; mi < 2; mi++)
            wmma::store_matrix_sync(Cp_s + ks * (B_SZ * CPLD) + (bw * 32 + mi * 16) * CPLD,
                                    fc[mi], CPLD, wmma::mem_row_major);
        __syncthreads();

        // ---- elementwise gated update (2 adjacent cells per thread) ----
        {
            float m_a0 = 0.f, m_a1 = 0.f, m_c0 = 0.f, m_c1 = 0.f;
#pragma unroll
            for (int q = 0; q < 4; q++) {
                const float* cp = Cp_s + q * (B_SZ * CPLD) + eb * CPLD;
                m_a0 += cp[ej];
                m_a1 += cp[ej + 1];
                m_c0 += cp[8 + ej];
                m_c1 += cp[8 + ej + 1];
            }
            float aa0 = 1.0f + tanhf(iA.x + m_a0);
            float cc0 = 1.0f / (1.0f + expf(-(iC.x + m_c0)));
            float hn0 = cc0 * h0 + (1.0f - cc0) * tanhf(iO.x + aa0 * h0);
            float aa1 = 1.0f + tanhf(iA.y + m_a1);
            float cc1 = 1.0f / (1.0f + expf(-(iC.y + m_c1)));
            float hn1 = cc1 * h1 + (1.0f - cc1) * tanhf(iO.y + aa1 * h1);
            h0 = hn0; h1 = hn1;

            float* os = out_seq + ((size_t)eb * L_SZ + step) * MEM + j0 + ej;
            *(float2*)os = make_float2(hn0, hn1);
            if (step == L_SZ - 1)
                *(float2*)(out_last + (size_t)eb * MEM + j0 + ej) = make_float2(hn0, hn1);
            stcg_f2(h_wr + (size_t)eb * MEM + j0 + ej, hn0, hn1);
        }

        // ---- grid barrier: release -> count -> acquire spin ----
        __threadfence();
        __syncthreads();
        bar_target += NCTA;
        if (t == 0) {
            asm volatile("red.release.gpu.global.add.u32 [%0], %1;"
                         :: "l"(&g_bar), "r"(1u) : "memory");
            unsigned v;
            do {
                asm volatile("ld.acquire.gpu.global.u32 %0, [%1];"
                             : "=r"(v) : "l"(&g_bar) : "memory");
            } while (v < bar_target);
        }
        __syncthreads();
        __threadfence();
    }
}

// ---------------- launch ----------------
extern "C" void kernel_launch(void* const* d_in, const int* in_sizes, int n_in,
                              void* d_out, int out_size) {
    const float* u   = (const float*)d_in[0];
    const float* Wim = (const float*)d_in[1];
    const float* Wmm = (const float*)d_in[2];
    float* out = (float*)d_out;
    float* out_seq  = out;
    float* out_last = out + (size_t)B_SZ * L_SZ * MEM;

    init_kernel<<<64, 256>>>();

    cudaFuncSetAttribute(gemm_in, cudaFuncAttributeMaxDynamicSharedMemorySize, GSMEM);
    dim3 ggrid((3 * MEM) / 64, (B_SZ * L_SZ) / 128);   // 48 x 256
    gemm_in<<<ggrid, 256, GSMEM>>>(u, Wim);

    cudaFuncSetAttribute(recur, cudaFuncAttributeMaxDynamicSharedMemorySize, RSMEM);
    recur<<<NCTA, RTHREADS, RSMEM>>>(Wmm, out_seq, out_last);
}